// round 1
// baseline (speedup 1.0000x reference)
#include <cuda_runtime.h>

#define N_NODE 4096
#define KNN 32
#define HIDDEN 128
#define RMS_EPS 1e-5f

__device__ int g_nbr[N_NODE * KNN];

static __device__ __forceinline__ unsigned long long ullmin2(unsigned long long a, unsigned long long b) {
    return (b < a) ? b : a;
}

// ---------------------------------------------------------------------------
// Kernel 1: kNN (32 nearest neighbors per node, excluding self).
// One block per node. Full distance row in SMEM, per-thread cached local min,
// 32 extract-min iterations; only the owner of the extracted index rescans.
// Packed key (distbits<<32 | idx) gives top_k's lower-index tie-break for free.
// ---------------------------------------------------------------------------
__global__ void knn_kernel(const float* __restrict__ pos) {
    __shared__ float sdist[N_NODE];
    __shared__ unsigned long long tbest[128];
    __shared__ unsigned long long wred[4];
    __shared__ int s_win;

    const int i = blockIdx.x;
    const int tid = threadIdx.x;
    const float px = pos[3 * i], py = pos[3 * i + 1], pz = pos[3 * i + 2];
    const float INF = __int_as_float(0x7f800000);

    for (int j = tid; j < N_NODE; j += 128) {
        float dx = px - pos[3 * j];
        float dy = py - pos[3 * j + 1];
        float dz = pz - pos[3 * j + 2];
        float d = fmaf(dx, dx, fmaf(dy, dy, dz * dz));
        sdist[j] = (j == i) ? INF : d;
    }
    __syncthreads();

    unsigned long long best = ~0ull;
    for (int j = tid; j < N_NODE; j += 128) {
        unsigned long long key =
            ((unsigned long long)__float_as_uint(sdist[j]) << 32) | (unsigned)j;
        best = ullmin2(best, key);
    }
    tbest[tid] = best;
    __syncthreads();

    for (int s = 0; s < KNN; s++) {
        unsigned long long v = tbest[tid];
        #pragma unroll
        for (int off = 16; off > 0; off >>= 1)
            v = ullmin2(v, __shfl_down_sync(0xffffffffu, v, off));
        if ((tid & 31) == 0) wred[tid >> 5] = v;
        __syncthreads();
        if (tid == 0) {
            unsigned long long b =
                ullmin2(ullmin2(wred[0], wred[1]), ullmin2(wred[2], wred[3]));
            int jw = (int)(b & 0xffffffffu);
            g_nbr[i * KNN + s] = jw;
            sdist[jw] = INF;
            s_win = jw;
        }
        __syncthreads();
        int owner = s_win & 127;
        if (tid == owner) {
            unsigned long long nb = ~0ull;
            for (int j = tid; j < N_NODE; j += 128) {
                unsigned long long key =
                    ((unsigned long long)__float_as_uint(sdist[j]) << 32) | (unsigned)j;
                nb = ullmin2(nb, key);
            }
            tbest[tid] = nb;
        }
        __syncthreads();
    }
}

// ---------------------------------------------------------------------------
// Kernel 2: fused per-edge MLP + local scatter-sum + output.
// One block per sender node (32 edges). 128 threads.
// Layer 1 uses the closed-form RMSNorm denominator (input is 1-D in radial).
// Layer 2 is a 32x128x128 GEMM with W2 in SMEM and packed fma.rn.f32x2.
// ---------------------------------------------------------------------------
__global__ void edge_kernel(const float* __restrict__ pos,
                            const float* __restrict__ t,
                            const float* __restrict__ W1,
                            const float* __restrict__ b1,
                            const float* __restrict__ g1,
                            const float* __restrict__ W2,
                            const float* __restrict__ b2,
                            const float* __restrict__ g2,
                            const float* __restrict__ W3,
                            const float* __restrict__ b3,
                            float* __restrict__ out) {
    extern __shared__ __align__(16) float sm[];
    float* W2s    = sm;                  // 128*129 = 16512
    float* h1s    = W2s + 128 * 129;     // 128*36 = 4608 (layout [k][e]; reused as y [m][e])
    float* sa     = h1s + 128 * 36;      // 128
    float* sc     = sa + 128;            // 128
    float* sg1    = sc + 128;            // 128
    float* sg2    = sg1 + 128;           // 128
    float* sW3    = sg2 + 128;           // 128
    float* cdx    = sW3 + 128;           // 32
    float* cdy    = cdx + 32;            // 32
    float* cdz    = cdy + 32;            // 32
    float* srs    = cdz + 32;            // 32 (radial)
    float* pbuf   = srs + 32;            // 128
    float* sscale = pbuf + 128;          // 32
    float* sABC   = sscale + 32;         // 4
    float* sred   = sABC + 4;            // 12

    const int i = blockIdx.x;
    const int tid = threadIdx.x;

    // --- Stage W2 into SMEM (row stride 129 floats -> conflict-free reads) ---
    for (int idx = tid; idx < HIDDEN * HIDDEN; idx += 128) {
        W2s[(idx >> 7) * 129 + (idx & 127)] = W2[idx];
    }

    // --- Per-channel params + A,B,C reduction for closed-form layer-1 RMSNorm ---
    {
        const int k = tid;
        float t0 = t[0];
        float a = W1[2 * k];
        float c = fmaf(t0, W1[2 * k + 1], b1[k]);
        sa[k] = a; sc[k] = c;
        sg1[k] = g1[k]; sg2[k] = g2[k]; sW3[k] = W3[k];
        float pa = a * a, pb = a * c, pc = c * c;
        #pragma unroll
        for (int off = 16; off > 0; off >>= 1) {
            pa += __shfl_down_sync(0xffffffffu, pa, off);
            pb += __shfl_down_sync(0xffffffffu, pb, off);
            pc += __shfl_down_sync(0xffffffffu, pc, off);
        }
        if ((tid & 31) == 0) {
            int w = tid >> 5;
            sred[w] = pa; sred[4 + w] = pb; sred[8 + w] = pc;
        }
    }

    // --- Edge geometry (32 edges of node i) ---
    if (tid < KNN) {
        int j = g_nbr[i * KNN + tid];
        float dx = pos[3 * i]     - pos[3 * j];
        float dy = pos[3 * i + 1] - pos[3 * j + 1];
        float dz = pos[3 * i + 2] - pos[3 * j + 2];
        cdx[tid] = dx; cdy[tid] = dy; cdz[tid] = dz;
        srs[tid] = fmaf(dx, dx, fmaf(dy, dy, dz * dz));
    }
    __syncthreads();

    if (tid == 0) {
        const float inv = 1.0f / HIDDEN;
        sABC[0] = (sred[0] + sred[1] + sred[2] + sred[3]) * inv;
        sABC[1] = (sred[4] + sred[5] + sred[6] + sred[7]) * inv;
        sABC[2] = (sred[8] + sred[9] + sred[10] + sred[11]) * inv;
    }
    __syncthreads();

    // --- Layer 1: h1[k][e] = silu(rmsnorm(r*a_k + c_k)) ---
    {
        const float A = sABC[0], B = sABC[1], C = sABC[2];
        const int e = tid & 31, kb = tid >> 5;
        float r = srs[e];
        float den = fmaf(fmaf(r, A, 2.0f * B), r, C) + RMS_EPS;
        float sscl = rsqrtf(den);
        for (int k = kb; k < HIDDEN; k += 4) {
            float x = fmaf(r, sa[k], sc[k]);
            float v = x * sscl * sg1[k];
            float h = v * (1.0f / (1.0f + __expf(-v)));
            h1s[k * 36 + e] = h;
        }
    }
    __syncthreads();

    // --- Layer 2 GEMM: y[e][m] = sum_k W2[m][k] * h1[e][k]; thread tid = channel m ---
    const int m = tid;
    unsigned long long acc[16];
    #pragma unroll
    for (int p = 0; p < 16; p++) acc[p] = 0ull;
    {
        const float* wrow = W2s + m * 129;
        #pragma unroll 4
        for (int k = 0; k < HIDDEN; k++) {
            float w = wrow[k];
            unsigned long long wp;
            asm("mov.b64 %0, {%1, %1};" : "=l"(wp) : "f"(w));
            const ulonglong2* hp = reinterpret_cast<const ulonglong2*>(h1s + k * 36);
            #pragma unroll
            for (int j = 0; j < 8; j++) {
                ulonglong2 v = hp[j];
                asm("fma.rn.f32x2 %0, %1, %2, %0;" : "+l"(acc[2 * j])     : "l"(wp), "l"(v.x));
                asm("fma.rn.f32x2 %0, %1, %2, %0;" : "+l"(acc[2 * j + 1]) : "l"(wp), "l"(v.y));
            }
        }
    }
    __syncthreads();  // everyone done reading h1s

    // --- Unpack y + bias into h1s reused as [m][e] ---
    {
        float bb = b2[m];
        #pragma unroll
        for (int j = 0; j < 16; j++) {
            float lo, hi;
            asm("mov.b64 {%0, %1}, %2;" : "=f"(lo), "=f"(hi) : "l"(acc[j]));
            h1s[m * 36 + 2 * j]     = lo + bb;
            h1s[m * 36 + 2 * j + 1] = hi + bb;
        }
    }
    __syncthreads();

    // --- Per-edge sum of y^2 over m (for layer-2 RMSNorm) ---
    {
        const int e = tid & 31, mb = tid >> 5;
        float ss = 0.0f;
        for (int mm = mb; mm < HIDDEN; mm += 4) {
            float y = h1s[mm * 36 + e];
            ss = fmaf(y, y, ss);
        }
        pbuf[mb * 32 + e] = ss;
    }
    __syncthreads();
    if (tid < 32) {
        float tot = pbuf[tid] + pbuf[32 + tid] + pbuf[64 + tid] + pbuf[96 + tid];
        sscale[tid] = rsqrtf(tot * (1.0f / HIDDEN) + RMS_EPS);
    }
    __syncthreads();

    // --- h2 = silu(y * scale * g2), dot with W3 ---
    {
        const int e = tid & 31, mb = tid >> 5;
        float scl = sscale[e];
        float dd = 0.0f;
        for (int mm = mb; mm < HIDDEN; mm += 4) {
            float y = h1s[mm * 36 + e];
            float v = y * scl * sg2[mm];
            float h = v * (1.0f / (1.0f + __expf(-v)));
            dd = fmaf(sW3[mm], h, dd);
        }
        pbuf[mb * 32 + e] = dd;
    }
    __syncthreads();

    // --- Scatter-sum (block-local) and final output ---
    if (tid < 32) {
        float scalar = pbuf[tid] + pbuf[32 + tid] + pbuf[64 + tid] + pbuf[96 + tid] + b3[0];
        float sx = cdx[tid] * scalar;
        float sy = cdy[tid] * scalar;
        float sz = cdz[tid] * scalar;
        #pragma unroll
        for (int off = 16; off > 0; off >>= 1) {
            sx += __shfl_down_sync(0xffffffffu, sx, off);
            sy += __shfl_down_sync(0xffffffffu, sy, off);
            sz += __shfl_down_sync(0xffffffffu, sz, off);
        }
        if (tid == 0) {
            const float invK = 1.0f / (float)KNN;
            out[3 * i]     = pos[3 * i]     + sx * invK;
            out[3 * i + 1] = pos[3 * i + 1] + sy * invK;
            out[3 * i + 2] = pos[3 * i + 2] + sz * invK;
        }
    }
}

// ---------------------------------------------------------------------------
// Launch
// ---------------------------------------------------------------------------
extern "C" void kernel_launch(void* const* d_in, const int* in_sizes, int n_in,
                              void* d_out, int out_size) {
    const float* pos = (const float*)d_in[0];
    const float* t   = (const float*)d_in[1];
    const float* W1  = (const float*)d_in[2];
    const float* b1  = (const float*)d_in[3];
    const float* g1  = (const float*)d_in[4];
    const float* W2  = (const float*)d_in[5];
    const float* b2  = (const float*)d_in[6];
    const float* g2  = (const float*)d_in[7];
    const float* W3  = (const float*)d_in[8];
    const float* b3  = (const float*)d_in[9];
    float* out = (float*)d_out;

    const int smem_bytes = (128 * 129 + 128 * 36 + 5 * 128 + 4 * 32 + 128 + 32 + 16) * 4;
    cudaFuncSetAttribute(edge_kernel, cudaFuncAttributeMaxDynamicSharedMemorySize, smem_bytes);

    knn_kernel<<<N_NODE, 128>>>(pos);
    edge_kernel<<<N_NODE, 128, smem_bytes>>>(pos, t, W1, b1, g1, W2, b2, g2, W3, b3, out);
}

// round 2
// speedup vs baseline: 1.7327x; 1.7327x over previous
#include <cuda_runtime.h>

#define N_NODE 4096
#define KNN 32
#define HIDDEN 128
#define RMS_EPS 1e-5f

__device__ int g_nbr[N_NODE * KNN];

typedef unsigned long long u64;

static __device__ __forceinline__ u64 ullmin2(u64 a, u64 b) { return (b < a) ? b : a; }

// ---------------------------------------------------------------------------
// Kernel 1: kNN via radix-select. One block (128 thr) per node.
// Histogram of float bits >> 20 (2048 buckets), prefix scan locates the bucket
// containing the 32nd smallest, one emission pass, warp-coop extract-min on the
// boundary bucket. Selected SET identical to serial extract-min (keys carry
// index for tie-break); order irrelevant (downstream is a sum).
// ---------------------------------------------------------------------------
__global__ void knn_kernel(const float* __restrict__ pos) {
    __shared__ float sdist[N_NODE];          // 16 KB
    __shared__ unsigned hist[2048];          // 8 KB
    __shared__ u64 cand[256];                // 2 KB
    __shared__ unsigned tsum[128];
    __shared__ int s_B;
    __shared__ unsigned s_base;
    __shared__ int s_ocnt, s_ccnt;

    const int i = blockIdx.x;
    const int tid = threadIdx.x;
    const float px = pos[3 * i], py = pos[3 * i + 1], pz = pos[3 * i + 2];
    const float INF = __int_as_float(0x7f800000);

    for (int b = tid; b < 2048; b += 128) hist[b] = 0;
    if (tid == 0) { s_ocnt = 0; s_ccnt = 0; }

    for (int j = tid; j < N_NODE; j += 128) {
        float dx = px - pos[3 * j];
        float dy = py - pos[3 * j + 1];
        float dz = pz - pos[3 * j + 2];
        float d = fmaf(dx, dx, fmaf(dy, dy, dz * dz));
        sdist[j] = (j == i) ? INF : d;
    }
    __syncthreads();

    // Histogram
    for (int j = tid; j < N_NODE; j += 128) {
        unsigned b = __float_as_uint(sdist[j]) >> 20;
        atomicAdd(&hist[b], 1u);
    }
    __syncthreads();

    // Prefix scan over 2048 buckets (16 per thread)
    {
        unsigned local = 0;
        const int b0 = tid * 16;
        #pragma unroll
        for (int q = 0; q < 16; q++) local += hist[b0 + q];
        tsum[tid] = local;
        __syncthreads();
        if (tid == 0) {
            unsigned run = 0;
            for (int w = 0; w < 128; w++) { unsigned c = tsum[w]; tsum[w] = run; run += c; }
        }
        __syncthreads();
        unsigned run = tsum[tid];
        #pragma unroll
        for (int q = 0; q < 16; q++) {
            unsigned h = hist[b0 + q];
            if (run < KNN && run + h >= KNN) { s_B = b0 + q; s_base = run; }
            run += h;
        }
    }
    __syncthreads();

    const int B = s_B;
    // Emission pass
    for (int j = tid; j < N_NODE; j += 128) {
        unsigned bits = __float_as_uint(sdist[j]);
        int b = (int)(bits >> 20);
        if (b < B) {
            int p = atomicAdd(&s_ocnt, 1);
            g_nbr[i * KNN + p] = j;
        } else if (b == B) {
            int c = atomicAdd(&s_ccnt, 1);
            if (c < 256) cand[c] = ((u64)bits << 32) | (unsigned)j;
        }
    }
    __syncthreads();

    // Pick remaining from boundary bucket (warp 0)
    if (tid < 32) {
        int ccnt = s_ccnt; if (ccnt > 256) ccnt = 256;
        int base = s_ocnt;           // == s_base
        int need = KNN - base;
        for (int s = 0; s < need; s++) {
            u64 best = ~0ull;
            for (int c = tid; c < ccnt; c += 32) best = ullmin2(best, cand[c]);
            #pragma unroll
            for (int off = 16; off > 0; off >>= 1)
                best = ullmin2(best, __shfl_down_sync(0xffffffffu, best, off));
            best = __shfl_sync(0xffffffffu, best, 0);
            if (tid == 0) {
                int j = (best == ~0ull) ? 0 : (int)(best & 0xffffffffu);
                g_nbr[i * KNN + base + s] = j;
            }
            for (int c = tid; c < ccnt; c += 32)
                if (cand[c] == best) cand[c] = ~0ull;
        }
    }
}

// ---------------------------------------------------------------------------
// Kernel 2: fused edge MLP + scatter. One block = 2 nodes (64 edges),
// 128 threads. Each thread owns 2 output channels of ONE node in the
// layer-2 GEMM (32 f32x2 accum each). W2 read directly from global (L2-hot).
// ---------------------------------------------------------------------------
__global__ void __launch_bounds__(128, 5)
edge_kernel(const float* __restrict__ pos,
            const float* __restrict__ t,
            const float* __restrict__ W1,
            const float* __restrict__ b1,
            const float* __restrict__ g1,
            const float* __restrict__ W2,
            const float* __restrict__ b2,
            const float* __restrict__ g2,
            const float* __restrict__ W3,
            const float* __restrict__ b3,
            float* __restrict__ out) {
    extern __shared__ __align__(16) float sm[];
    float* h1sA   = sm;                   // 128*36  (node A: [k][e]; reused as y [m][e])
    float* h1sB   = h1sA + 128 * 36;      // 128*36  (node B)
    float* sa     = h1sB + 128 * 36;      // 128
    float* sc     = sa + 128;             // 128
    float* sg1    = sc + 128;             // 128
    float* sg2    = sg1 + 128;            // 128
    float* sW3    = sg2 + 128;            // 128
    float* cdx    = sW3 + 128;            // 64
    float* cdy    = cdx + 64;             // 64
    float* cdz    = cdy + 64;             // 64
    float* srs    = cdz + 64;             // 64 (radial per edge)
    float* pbuf   = srs + 64;             // 128
    float* sscale = pbuf + 128;           // 64
    float* sABC   = sscale + 64;          // 4
    float* sred   = sABC + 4;             // 12

    const int tid = threadIdx.x;
    const int iA = blockIdx.x * 2;

    // --- Per-channel params + A,B,C (weights-only closed-form L1 RMSNorm) ---
    {
        const int k = tid;
        float t0 = t[0];
        float a = W1[2 * k];
        float c = fmaf(t0, W1[2 * k + 1], b1[k]);
        sa[k] = a; sc[k] = c;
        sg1[k] = g1[k]; sg2[k] = g2[k]; sW3[k] = W3[k];
        float pa = a * a, pb = a * c, pc = c * c;
        #pragma unroll
        for (int off = 16; off > 0; off >>= 1) {
            pa += __shfl_down_sync(0xffffffffu, pa, off);
            pb += __shfl_down_sync(0xffffffffu, pb, off);
            pc += __shfl_down_sync(0xffffffffu, pc, off);
        }
        if ((tid & 31) == 0) {
            int w = tid >> 5;
            sred[w] = pa; sred[4 + w] = pb; sred[8 + w] = pc;
        }
    }

    // --- Edge geometry: 64 edges (2 nodes x 32) ---
    if (tid < 64) {
        int node = tid >> 5, e = tid & 31;
        int i = iA + node;
        int j = g_nbr[i * KNN + e];
        float dx = pos[3 * i]     - pos[3 * j];
        float dy = pos[3 * i + 1] - pos[3 * j + 1];
        float dz = pos[3 * i + 2] - pos[3 * j + 2];
        cdx[tid] = dx; cdy[tid] = dy; cdz[tid] = dz;
        srs[tid] = fmaf(dx, dx, fmaf(dy, dy, dz * dz));
    }
    __syncthreads();

    if (tid == 0) {
        const float inv = 1.0f / HIDDEN;
        sABC[0] = (sred[0] + sred[1] + sred[2] + sred[3]) * inv;
        sABC[1] = (sred[4] + sred[5] + sred[6] + sred[7]) * inv;
        sABC[2] = (sred[8] + sred[9] + sred[10] + sred[11]) * inv;
    }
    __syncthreads();

    // --- Layer 1: h1[node][k][e] = silu(rmsnorm(r*a_k + c_k)) ---
    {
        const float A = sABC[0], B = sABC[1], C = sABC[2];
        const int e64 = tid & 63, kb = tid >> 6;       // edge, k-offset
        const int eloc = e64 & 31;
        float* hb = (e64 < 32) ? h1sA : h1sB;
        float r = srs[e64];
        float den = fmaf(fmaf(r, A, 2.0f * B), r, C) + RMS_EPS;
        float sscl = rsqrtf(den);
        for (int k = kb; k < HIDDEN; k += 2) {
            float x = fmaf(r, sa[k], sc[k]);
            float v = x * sscl * sg1[k];
            float h = v * (1.0f / (1.0f + __expf(-v)));
            hb[k * 36 + eloc] = h;
        }
    }
    __syncthreads();

    // --- Layer 2 GEMM: thread owns channels (m0, m0+64) of one node ---
    const int node = tid >> 6;          // 0: node A, 1: node B
    const int m0 = tid & 63;
    const int m1 = m0 + 64;
    const float* __restrict__ hb = node ? h1sB : h1sA;

    u64 acc0[16], acc1[16];
    #pragma unroll
    for (int p = 0; p < 16; p++) { acc0[p] = 0ull; acc1[p] = 0ull; }
    {
        const float4* __restrict__ w0v = (const float4*)(W2 + m0 * HIDDEN);
        const float4* __restrict__ w1v = (const float4*)(W2 + m1 * HIDDEN);
        #pragma unroll 2
        for (int kk = 0; kk < 32; kk++) {
            float4 a0 = __ldg(w0v + kk);
            float4 a1 = __ldg(w1v + kk);
            float w0a[4] = {a0.x, a0.y, a0.z, a0.w};
            float w1a[4] = {a1.x, a1.y, a1.z, a1.w};
            #pragma unroll
            for (int q = 0; q < 4; q++) {
                int k = 4 * kk + q;
                u64 wp0, wp1;
                asm("mov.b64 %0, {%1, %1};" : "=l"(wp0) : "f"(w0a[q]));
                asm("mov.b64 %0, {%1, %1};" : "=l"(wp1) : "f"(w1a[q]));
                const ulonglong2* hp = reinterpret_cast<const ulonglong2*>(hb + k * 36);
                #pragma unroll
                for (int j = 0; j < 8; j++) {
                    ulonglong2 v = hp[j];
                    asm("fma.rn.f32x2 %0, %1, %2, %0;" : "+l"(acc0[2 * j])     : "l"(wp0), "l"(v.x));
                    asm("fma.rn.f32x2 %0, %1, %2, %0;" : "+l"(acc0[2 * j + 1]) : "l"(wp0), "l"(v.y));
                    asm("fma.rn.f32x2 %0, %1, %2, %0;" : "+l"(acc1[2 * j])     : "l"(wp1), "l"(v.x));
                    asm("fma.rn.f32x2 %0, %1, %2, %0;" : "+l"(acc1[2 * j + 1]) : "l"(wp1), "l"(v.y));
                }
            }
        }
    }
    __syncthreads();   // all reads of h1 done

    // --- Unpack y + bias into [m][e] (same buffers) ---
    {
        float bb0 = b2[m0], bb1 = b2[m1];
        float* yb = node ? h1sB : h1sA;
        #pragma unroll
        for (int j = 0; j < 16; j++) {
            float lo, hi;
            asm("mov.b64 {%0, %1}, %2;" : "=f"(lo), "=f"(hi) : "l"(acc0[j]));
            yb[m0 * 36 + 2 * j]     = lo + bb0;
            yb[m0 * 36 + 2 * j + 1] = hi + bb0;
            asm("mov.b64 {%0, %1}, %2;" : "=f"(lo), "=f"(hi) : "l"(acc1[j]));
            yb[m1 * 36 + 2 * j]     = lo + bb1;
            yb[m1 * 36 + 2 * j + 1] = hi + bb1;
        }
    }
    __syncthreads();

    // --- Per-edge sum of y^2 over channels (layer-2 RMSNorm) ---
    {
        const int e64 = tid & 63, half = tid >> 6;   // edge, channel-half
        const int eloc = e64 & 31;
        const float* yb = (e64 < 32) ? h1sA : h1sB;
        float ss = 0.0f;
        #pragma unroll 4
        for (int m = half * 64; m < half * 64 + 64; m++) {
            float y = yb[m * 36 + eloc];
            ss = fmaf(y, y, ss);
        }
        pbuf[half * 64 + e64] = ss;
    }
    __syncthreads();
    if (tid < 64) {
        float tot = pbuf[tid] + pbuf[64 + tid];
        sscale[tid] = rsqrtf(tot * (1.0f / HIDDEN) + RMS_EPS);
    }
    __syncthreads();

    // --- h2 = silu(y * scale * g2), dot with W3 ---
    {
        const int e64 = tid & 63, half = tid >> 6;
        const int eloc = e64 & 31;
        const float* yb = (e64 < 32) ? h1sA : h1sB;
        float scl = sscale[e64];
        float dd = 0.0f;
        #pragma unroll 4
        for (int m = half * 64; m < half * 64 + 64; m++) {
            float y = yb[m * 36 + eloc];
            float v = y * scl * sg2[m];
            float h = v * (1.0f / (1.0f + __expf(-v)));
            dd = fmaf(sW3[m], h, dd);
        }
        pbuf[half * 64 + e64] = dd;
    }
    __syncthreads();

    // --- Block-local scatter-sum (per node via one warp each) + output ---
    if (tid < 64) {
        float scalar = pbuf[tid] + pbuf[64 + tid] + b3[0];
        float sx = cdx[tid] * scalar;
        float sy = cdy[tid] * scalar;
        float sz = cdz[tid] * scalar;
        #pragma unroll
        for (int off = 16; off > 0; off >>= 1) {
            sx += __shfl_down_sync(0xffffffffu, sx, off);
            sy += __shfl_down_sync(0xffffffffu, sy, off);
            sz += __shfl_down_sync(0xffffffffu, sz, off);
        }
        if ((tid & 31) == 0) {
            int i = iA + (tid >> 5);
            const float invK = 1.0f / (float)KNN;
            out[3 * i]     = pos[3 * i]     + sx * invK;
            out[3 * i + 1] = pos[3 * i + 1] + sy * invK;
            out[3 * i + 2] = pos[3 * i + 2] + sz * invK;
        }
    }
}

// ---------------------------------------------------------------------------
// Launch
// ---------------------------------------------------------------------------
extern "C" void kernel_launch(void* const* d_in, const int* in_sizes, int n_in,
                              void* d_out, int out_size) {
    const float* pos = (const float*)d_in[0];
    const float* t   = (const float*)d_in[1];
    const float* W1  = (const float*)d_in[2];
    const float* b1  = (const float*)d_in[3];
    const float* g1  = (const float*)d_in[4];
    const float* W2  = (const float*)d_in[5];
    const float* b2  = (const float*)d_in[6];
    const float* g2  = (const float*)d_in[7];
    const float* W3  = (const float*)d_in[8];
    const float* b3  = (const float*)d_in[9];
    float* out = (float*)d_out;

    const int smem_bytes = (2 * 128 * 36 + 5 * 128 + 4 * 64 + 128 + 64 + 32) * 4;
    cudaFuncSetAttribute(edge_kernel, cudaFuncAttributeMaxDynamicSharedMemorySize, smem_bytes);

    knn_kernel<<<N_NODE, 128>>>(pos);
    edge_kernel<<<N_NODE / 2, 128, smem_bytes>>>(pos, t, W1, b1, g1, W2, b2, g2, W3, b3, out);
}

// round 3
// speedup vs baseline: 4.5402x; 2.6203x over previous
#include <cuda_runtime.h>

#define N_NODE 4096
#define KNN 32
#define HIDDEN 128
#define RMS_EPS 1e-5f
#define TABLE_N 8192

__device__ int g_nbr[N_NODE * KNN];
__device__ unsigned g_rmax_bits;
__device__ float g_table[TABLE_N];
__device__ float4 g_pos4[N_NODE];

typedef unsigned long long u64;

static __device__ __forceinline__ u64 ullmin2(u64 a, u64 b) { return (b < a) ? b : a; }

// ---------------------------------------------------------------------------
// Kernel 0: pack pos into float4 + reset rmax.
// ---------------------------------------------------------------------------
__global__ void prep_kernel(const float* __restrict__ pos) {
    int j = blockIdx.x * blockDim.x + threadIdx.x;
    if (j < N_NODE)
        g_pos4[j] = make_float4(pos[3 * j], pos[3 * j + 1], pos[3 * j + 2], 0.0f);
    if (j == 0) g_rmax_bits = 0u;
}

// ---------------------------------------------------------------------------
// Kernel 1: kNN via radix-select (one block / node) + global max of selected
// distance (the per-node 32nd-smallest lives in the boundary bucket; its last
// extraction is the node's max; atomicMax over nodes gives exact r_max).
// ---------------------------------------------------------------------------
__global__ void knn_kernel() {
    __shared__ float sdist[N_NODE];          // 16 KB
    __shared__ unsigned hist[2048];          // 8 KB
    __shared__ u64 cand[256];                // 2 KB
    __shared__ unsigned tsum[128];
    __shared__ int s_B;
    __shared__ int s_ocnt, s_ccnt;

    const int i = blockIdx.x;
    const int tid = threadIdx.x;
    const float4 pi = g_pos4[i];
    const float INF = __int_as_float(0x7f800000);

    for (int b = tid; b < 2048; b += 128) hist[b] = 0;
    if (tid == 0) { s_ocnt = 0; s_ccnt = 0; }
    __syncthreads();

    // Distances + histogram (fused)
    for (int j = tid; j < N_NODE; j += 128) {
        float4 q = g_pos4[j];
        float dx = pi.x - q.x, dy = pi.y - q.y, dz = pi.z - q.z;
        float d = fmaf(dx, dx, fmaf(dy, dy, dz * dz));
        d = (j == i) ? INF : d;
        sdist[j] = d;
        atomicAdd(&hist[__float_as_uint(d) >> 20], 1u);
    }
    __syncthreads();

    // Prefix scan over 2048 buckets (16 per thread)
    {
        unsigned local = 0;
        const int b0 = tid * 16;
        #pragma unroll
        for (int q = 0; q < 16; q++) local += hist[b0 + q];
        tsum[tid] = local;
        __syncthreads();
        if (tid == 0) {
            unsigned run = 0;
            for (int w = 0; w < 128; w++) { unsigned c = tsum[w]; tsum[w] = run; run += c; }
        }
        __syncthreads();
        unsigned run = tsum[tid];
        #pragma unroll
        for (int q = 0; q < 16; q++) {
            unsigned h = hist[b0 + q];
            if (run < KNN && run + h >= KNN) s_B = b0 + q;
            run += h;
        }
    }
    __syncthreads();

    const int B = s_B;
    // Emission pass
    for (int j = tid; j < N_NODE; j += 128) {
        unsigned bits = __float_as_uint(sdist[j]);
        int b = (int)(bits >> 20);
        if (b < B) {
            int p = atomicAdd(&s_ocnt, 1);
            g_nbr[i * KNN + p] = j;
        } else if (b == B) {
            int c = atomicAdd(&s_ccnt, 1);
            if (c < 256) cand[c] = ((u64)bits << 32) | (unsigned)j;
        }
    }
    __syncthreads();

    // Extract remaining from boundary bucket (warp 0); track node max.
    if (tid < 32) {
        int ccnt = s_ccnt; if (ccnt > 256) ccnt = 256;
        int base = s_ocnt;
        int need = KNN - base;
        u64 last = 0;
        for (int s = 0; s < need; s++) {
            u64 best = ~0ull;
            for (int c = tid; c < ccnt; c += 32) best = ullmin2(best, cand[c]);
            #pragma unroll
            for (int off = 16; off > 0; off >>= 1)
                best = ullmin2(best, __shfl_down_sync(0xffffffffu, best, off));
            best = __shfl_sync(0xffffffffu, best, 0);
            if (tid == 0) {
                int j = (best == ~0ull) ? 0 : (int)(best & 0xffffffffu);
                g_nbr[i * KNN + base + s] = j;
            }
            for (int c = tid; c < ccnt; c += 32)
                if (cand[c] == best) cand[c] = ~0ull;
            last = best;
        }
        if (tid == 0 && need > 0 && last != ~0ull)
            atomicMax(&g_rmax_bits, (unsigned)(last >> 32));
    }
}

// ---------------------------------------------------------------------------
// Kernel 2: tabulate s(r) at TABLE_N points on [0, rmax].
// One block = 64 samples (two groups of 32), 128 threads; thread owns 2
// channels of one group in the layer-2 GEMM (f32x2 FMA), W2 from L2.
// ---------------------------------------------------------------------------
__global__ void __launch_bounds__(128, 5)
table_kernel(const float* __restrict__ t,
             const float* __restrict__ W1,
             const float* __restrict__ b1,
             const float* __restrict__ g1,
             const float* __restrict__ W2,
             const float* __restrict__ b2,
             const float* __restrict__ g2,
             const float* __restrict__ W3,
             const float* __restrict__ b3) {
    extern __shared__ __align__(16) float sm[];
    float* h1sA   = sm;                   // 128*36
    float* h1sB   = h1sA + 128 * 36;      // 128*36
    float* sa     = h1sB + 128 * 36;      // 128
    float* sc     = sa + 128;             // 128
    float* sg1    = sc + 128;             // 128
    float* sg2    = sg1 + 128;            // 128
    float* sW3    = sg2 + 128;            // 128
    float* srs    = sW3 + 128;            // 64
    float* pbuf   = srs + 64;             // 128
    float* sscale = pbuf + 128;           // 64
    float* sABC   = sscale + 64;          // 4
    float* sred   = sABC + 4;             // 12

    const int tid = threadIdx.x;
    const int base = blockIdx.x * 64;

    // --- Per-channel params + A,B,C (closed-form L1 RMSNorm denominator) ---
    {
        const int k = tid;
        float t0 = t[0];
        float a = W1[2 * k];
        float c = fmaf(t0, W1[2 * k + 1], b1[k]);
        sa[k] = a; sc[k] = c;
        sg1[k] = g1[k]; sg2[k] = g2[k]; sW3[k] = W3[k];
        float pa = a * a, pb = a * c, pc = c * c;
        #pragma unroll
        for (int off = 16; off > 0; off >>= 1) {
            pa += __shfl_down_sync(0xffffffffu, pa, off);
            pb += __shfl_down_sync(0xffffffffu, pb, off);
            pc += __shfl_down_sync(0xffffffffu, pc, off);
        }
        if ((tid & 31) == 0) {
            int w = tid >> 5;
            sred[w] = pa; sred[4 + w] = pb; sred[8 + w] = pc;
        }
    }

    // --- Sample radials ---
    if (tid < 64) {
        float rmax = __uint_as_float(g_rmax_bits);
        float step = rmax * (1.0f / (float)(TABLE_N - 1));
        srs[tid] = step * (float)(base + tid);
    }
    __syncthreads();

    if (tid == 0) {
        const float inv = 1.0f / HIDDEN;
        sABC[0] = (sred[0] + sred[1] + sred[2] + sred[3]) * inv;
        sABC[1] = (sred[4] + sred[5] + sred[6] + sred[7]) * inv;
        sABC[2] = (sred[8] + sred[9] + sred[10] + sred[11]) * inv;
    }
    __syncthreads();

    // --- Layer 1 ---
    {
        const float A = sABC[0], B = sABC[1], C = sABC[2];
        const int e64 = tid & 63, kb = tid >> 6;
        const int eloc = e64 & 31;
        float* hb = (e64 < 32) ? h1sA : h1sB;
        float r = srs[e64];
        float den = fmaf(fmaf(r, A, 2.0f * B), r, C) + RMS_EPS;
        float sscl = rsqrtf(den);
        for (int k = kb; k < HIDDEN; k += 2) {
            float x = fmaf(r, sa[k], sc[k]);
            float v = x * sscl * sg1[k];
            float h = v * (1.0f / (1.0f + __expf(-v)));
            hb[k * 36 + eloc] = h;
        }
    }
    __syncthreads();

    // --- Layer 2 GEMM: thread owns channels (m0, m0+64) of one sample group ---
    const int node = tid >> 6;
    const int m0 = tid & 63;
    const int m1 = m0 + 64;
    const float* __restrict__ hb = node ? h1sB : h1sA;

    u64 acc0[16], acc1[16];
    #pragma unroll
    for (int p = 0; p < 16; p++) { acc0[p] = 0ull; acc1[p] = 0ull; }
    {
        const float4* __restrict__ w0v = (const float4*)(W2 + m0 * HIDDEN);
        const float4* __restrict__ w1v = (const float4*)(W2 + m1 * HIDDEN);
        #pragma unroll 2
        for (int kk = 0; kk < 32; kk++) {
            float4 a0 = __ldg(w0v + kk);
            float4 a1 = __ldg(w1v + kk);
            float w0a[4] = {a0.x, a0.y, a0.z, a0.w};
            float w1a[4] = {a1.x, a1.y, a1.z, a1.w};
            #pragma unroll
            for (int q = 0; q < 4; q++) {
                int k = 4 * kk + q;
                u64 wp0, wp1;
                asm("mov.b64 %0, {%1, %1};" : "=l"(wp0) : "f"(w0a[q]));
                asm("mov.b64 %0, {%1, %1};" : "=l"(wp1) : "f"(w1a[q]));
                const ulonglong2* hp = reinterpret_cast<const ulonglong2*>(hb + k * 36);
                #pragma unroll
                for (int j = 0; j < 8; j++) {
                    ulonglong2 v = hp[j];
                    asm("fma.rn.f32x2 %0, %1, %2, %0;" : "+l"(acc0[2 * j])     : "l"(wp0), "l"(v.x));
                    asm("fma.rn.f32x2 %0, %1, %2, %0;" : "+l"(acc0[2 * j + 1]) : "l"(wp0), "l"(v.y));
                    asm("fma.rn.f32x2 %0, %1, %2, %0;" : "+l"(acc1[2 * j])     : "l"(wp1), "l"(v.x));
                    asm("fma.rn.f32x2 %0, %1, %2, %0;" : "+l"(acc1[2 * j + 1]) : "l"(wp1), "l"(v.y));
                }
            }
        }
    }
    __syncthreads();

    // --- Unpack y + bias ---
    {
        float bb0 = b2[m0], bb1 = b2[m1];
        float* yb = node ? h1sB : h1sA;
        #pragma unroll
        for (int j = 0; j < 16; j++) {
            float lo, hi;
            asm("mov.b64 {%0, %1}, %2;" : "=f"(lo), "=f"(hi) : "l"(acc0[j]));
            yb[m0 * 36 + 2 * j]     = lo + bb0;
            yb[m0 * 36 + 2 * j + 1] = hi + bb0;
            asm("mov.b64 {%0, %1}, %2;" : "=f"(lo), "=f"(hi) : "l"(acc1[j]));
            yb[m1 * 36 + 2 * j]     = lo + bb1;
            yb[m1 * 36 + 2 * j + 1] = hi + bb1;
        }
    }
    __syncthreads();

    // --- Per-sample sum of y^2 (layer-2 RMSNorm) ---
    {
        const int e64 = tid & 63, half = tid >> 6;
        const int eloc = e64 & 31;
        const float* yb = (e64 < 32) ? h1sA : h1sB;
        float ss = 0.0f;
        #pragma unroll 4
        for (int m = half * 64; m < half * 64 + 64; m++) {
            float y = yb[m * 36 + eloc];
            ss = fmaf(y, y, ss);
        }
        pbuf[half * 64 + e64] = ss;
    }
    __syncthreads();
    if (tid < 64) {
        float tot = pbuf[tid] + pbuf[64 + tid];
        sscale[tid] = rsqrtf(tot * (1.0f / HIDDEN) + RMS_EPS);
    }
    __syncthreads();

    // --- h2 = silu(y*scale*g2) dot W3 ---
    {
        const int e64 = tid & 63, half = tid >> 6;
        const int eloc = e64 & 31;
        const float* yb = (e64 < 32) ? h1sA : h1sB;
        float scl = sscale[e64];
        float dd = 0.0f;
        #pragma unroll 4
        for (int m = half * 64; m < half * 64 + 64; m++) {
            float y = yb[m * 36 + eloc];
            float v = y * scl * sg2[m];
            float h = v * (1.0f / (1.0f + __expf(-v)));
            dd = fmaf(sW3[m], h, dd);
        }
        pbuf[half * 64 + e64] = dd;
    }
    __syncthreads();

    if (tid < 64)
        g_table[base + tid] = pbuf[tid] + pbuf[64 + tid] + b3[0];
}

// ---------------------------------------------------------------------------
// Kernel 3: per-edge evaluation via table lerp + block-local scatter.
// One warp per node.
// ---------------------------------------------------------------------------
__global__ void eval_kernel(const float* __restrict__ pos, float* __restrict__ out) {
    const int gw = (blockIdx.x * blockDim.x + threadIdx.x) >> 5;
    const int lane = threadIdx.x & 31;
    if (gw >= N_NODE) return;
    const int i = gw;

    float4 pi = g_pos4[i];
    int j = g_nbr[i * KNN + lane];
    float4 pj = g_pos4[j];
    float dx = pi.x - pj.x, dy = pi.y - pj.y, dz = pi.z - pj.z;
    float r = fmaf(dx, dx, fmaf(dy, dy, dz * dz));

    float rmax = __uint_as_float(g_rmax_bits);
    float scale = (rmax > 0.0f) ? ((float)(TABLE_N - 1) / rmax) : 0.0f;
    float u = r * scale;
    if (u > (float)(TABLE_N - 1)) u = (float)(TABLE_N - 1);
    int i0 = (int)u;
    if (i0 > TABLE_N - 2) i0 = TABLE_N - 2;
    float f = u - (float)i0;
    float s0 = g_table[i0], s1 = g_table[i0 + 1];
    float s = fmaf(f, s1 - s0, s0);

    float sx = dx * s, sy = dy * s, sz = dz * s;
    #pragma unroll
    for (int off = 16; off > 0; off >>= 1) {
        sx += __shfl_down_sync(0xffffffffu, sx, off);
        sy += __shfl_down_sync(0xffffffffu, sy, off);
        sz += __shfl_down_sync(0xffffffffu, sz, off);
    }
    if (lane == 0) {
        const float invK = 1.0f / (float)KNN;
        out[3 * i]     = pi.x + sx * invK;
        out[3 * i + 1] = pi.y + sy * invK;
        out[3 * i + 2] = pi.z + sz * invK;
    }
}

// ---------------------------------------------------------------------------
// Launch
// ---------------------------------------------------------------------------
extern "C" void kernel_launch(void* const* d_in, const int* in_sizes, int n_in,
                              void* d_out, int out_size) {
    const float* pos = (const float*)d_in[0];
    const float* t   = (const float*)d_in[1];
    const float* W1  = (const float*)d_in[2];
    const float* b1  = (const float*)d_in[3];
    const float* g1  = (const float*)d_in[4];
    const float* W2  = (const float*)d_in[5];
    const float* b2  = (const float*)d_in[6];
    const float* g2  = (const float*)d_in[7];
    const float* W3  = (const float*)d_in[8];
    const float* b3  = (const float*)d_in[9];
    float* out = (float*)d_out;

    const int smem_bytes = (2 * 128 * 36 + 5 * 128 + 64 + 128 + 64 + 16) * 4;
    cudaFuncSetAttribute(table_kernel, cudaFuncAttributeMaxDynamicSharedMemorySize, smem_bytes);

    prep_kernel<<<(N_NODE + 255) / 256, 256>>>(pos);
    knn_kernel<<<N_NODE, 128>>>();
    table_kernel<<<TABLE_N / 64, 128, smem_bytes>>>(t, W1, b1, g1, W2, b2, g2, W3, b3);
    eval_kernel<<<(N_NODE * 32) / 256, 256>>>(pos, out);
}